// round 9
// baseline (speedup 1.0000x reference)
#include <cuda_runtime.h>
#include <cuda_bf16.h>
#include <mma.h>
#include <cstdint>
#include <math.h>

using namespace nvcuda;

#define BATCH 32768
#define NLEN  1116
#define HDIM  100

// ---------------------------------------------------------------------------
// sym4 filters
// ---------------------------------------------------------------------------
__constant__ float c_LO[8] = {
    -0.010597401784997278f,  0.032883011666982945f,  0.030841381835986965f,
    -0.18703481171888114f,  -0.02798376941698385f,   0.6308807679295904f,
     0.7148465705525415f,    0.23037781330885523f};
__constant__ float c_HI[8] = {
    -0.23037781330885523f,   0.7148465705525415f,   -0.6308807679295904f,
    -0.02798376941698385f,   0.18703481171888114f,   0.030841381835986965f,
    -0.032883011666982945f, -0.010597401784997278f};

__device__ __forceinline__ float softt(float v, float t) {
    float av = fabsf(v);
    return (av > t) ? copysignf(av - t, v) : 0.0f;
}

// One DWT level: T threads, id in [0,T); input cur (data at +8, xp[i]==cur[2+i]),
// outputs: approx -> nxt[8..], thresholded detail -> dd[0..m)
template <int T>
__device__ __forceinline__ void dwt_level(const float* cur, float* nxt, float* dd,
                                          int m, int id, float t)
{
    const int chunk = ((m + T - 1) / T) | 1;   // odd -> <=2-way LDS conflicts
    const int j0 = id * chunk;
    const int je = (j0 + chunk < m) ? (j0 + chunk) : m;
    if (j0 < je) {
        const float* p = cur + 2 + 2 * j0;
        float w0 = p[0], w1 = p[1], w2 = p[2], w3 = p[3];
        float w4 = p[4], w5 = p[5], w6 = p[6], w7 = p[7];
        int idx = 8;
        for (int j = j0; j < je; ++j) {
            float lo = w0 * c_LO[7];
            lo = fmaf(w1, c_LO[6], lo); lo = fmaf(w2, c_LO[5], lo);
            lo = fmaf(w3, c_LO[4], lo); lo = fmaf(w4, c_LO[3], lo);
            lo = fmaf(w5, c_LO[2], lo); lo = fmaf(w6, c_LO[1], lo);
            lo = fmaf(w7, c_LO[0], lo);
            float hi = w0 * c_HI[7];
            hi = fmaf(w1, c_HI[6], hi); hi = fmaf(w2, c_HI[5], hi);
            hi = fmaf(w3, c_HI[4], hi); hi = fmaf(w4, c_HI[3], hi);
            hi = fmaf(w5, c_HI[2], hi); hi = fmaf(w6, c_HI[1], hi);
            hi = fmaf(w7, c_HI[0], hi);
            nxt[8 + j] = lo;
            dd[j] = softt(hi, t);
            w0 = w2; w1 = w3; w2 = w4; w3 = w5; w4 = w6; w5 = w7;
            w6 = p[idx]; w7 = p[idx + 1]; idx += 2;   // lookahead (array slack)
        }
    }
    if (id < 6) nxt[2 + id] = 0.0f;
    if (id < 8) nxt[8 + m + id] = 0.0f;
}

// One IDWT level: a at abase[0..], d at dd[0..], output pairs to obase.
template <int T>
__device__ __forceinline__ void idwt_level(const float* abase, const float* dd,
                                           float* obase, int pairs, int id)
{
    const int chunk = ((pairs + T - 1) / T) | 1;
    const int p0 = id * chunk;
    const int pe = (p0 + chunk < pairs) ? (p0 + chunk) : pairs;
    if (p0 < pe) {
        float a0 = abase[p0], a1 = abase[p0 + 1], a2 = abase[p0 + 2], a3 = abase[p0 + 3];
        float d0 = dd[p0],    d1 = dd[p0 + 1],    d2 = dd[p0 + 2],    d3 = dd[p0 + 3];
        for (int p = p0; p < pe; ++p) {
            float ye = a0 * c_LO[1];
            ye = fmaf(a1, c_LO[3], ye); ye = fmaf(a2, c_LO[5], ye); ye = fmaf(a3, c_LO[7], ye);
            ye = fmaf(d0, c_HI[1], ye); ye = fmaf(d1, c_HI[3], ye);
            ye = fmaf(d2, c_HI[5], ye); ye = fmaf(d3, c_HI[7], ye);
            float yo = a0 * c_LO[0];
            yo = fmaf(a1, c_LO[2], yo); yo = fmaf(a2, c_LO[4], yo); yo = fmaf(a3, c_LO[6], yo);
            yo = fmaf(d0, c_HI[0], yo); yo = fmaf(d1, c_HI[2], yo);
            yo = fmaf(d2, c_HI[4], yo); yo = fmaf(d3, c_HI[6], yo);
            ((float2*)obase)[p] = make_float2(ye, yo);
            a0 = a1; a1 = a2; a2 = a3; a3 = abase[p + 4];   // lookahead ok
            d0 = d1; d1 = d2; d2 = d3; d3 = dd[p + 4];
        }
    }
}

// ---------------------------------------------------------------------------
// Kernel 1: per-row 7-level DWT -> soft threshold -> IDWT.
// One 128-thread block per row. Shallow levels (big m): full block + barrier.
// Deep levels (analysis l3-l6, soft, synthesis l6-l4): WARP 0 ONLY with
// __syncwarp, other warps sleep at one rejoin barrier.
// Levels: 1116 -> 561 -> 284 -> 145 -> 76 -> 41 -> 24 -> 15
// ---------------------------------------------------------------------------
__global__ __launch_bounds__(128) void wavelet_kernel(
    const float* __restrict__ x,
    const float* __restrict__ thr,
    float* __restrict__ recon)
{
    __shared__ __align__(16) float bufA[1140];
    __shared__ __align__(16) float bufB[1140];
    __shared__ __align__(16) float dbuf[1152];

    const int tid = threadIdx.x;
    const int row = blockIdx.x;
    const float t = fmaxf(thr[0], 0.01f);

    const int ns[8]   = {1116, 561, 284, 145, 76, 41, 24, 15};
    const int doff[7] = {0, 561, 845, 990, 1066, 1107, 1131};

    // Load row (vectorized): 1116 = 279 float4
    {
        const float4* xr = (const float4*)(x + (size_t)row * NLEN);
        float4* dst = (float4*)(bufA + 8);
        for (int i = tid; i < 279; i += 128) dst[i] = xr[i];
        if (tid < 6) bufA[2 + tid] = 0.0f;
        if (tid < 8) bufA[8 + NLEN + tid] = 0.0f;
    }
    __syncthreads();

    // ----- Analysis l0..l2 (full block) -----
    // cur/nxt ping-pong: bufA -> bufB -> bufA -> bufB (a3 in bufB)
    dwt_level<128>(bufA, bufB, dbuf + doff[0], ns[1], tid, t);
    __syncthreads();
    dwt_level<128>(bufB, bufA, dbuf + doff[1], ns[2], tid, t);
    __syncthreads();
    dwt_level<128>(bufA, bufB, dbuf + doff[2], ns[3], tid, t);
    __syncthreads();

    // ----- Deep phase: warp 0 only -----
    if (tid < 32) {
        const int lane = tid;
        // analysis l3..l6: bufB->bufA->bufB->bufA->bufB (a7 in bufB at +8)
        dwt_level<32>(bufB, bufA, dbuf + doff[3], ns[4], lane, t);
        __syncwarp();
        dwt_level<32>(bufA, bufB, dbuf + doff[4], ns[5], lane, t);
        __syncwarp();
        dwt_level<32>(bufB, bufA, dbuf + doff[5], ns[6], lane, t);
        __syncwarp();
        dwt_level<32>(bufA, bufB, dbuf + doff[6], ns[7], lane, t);
        __syncwarp();
        // soft-threshold final approx (len 15)
        if (lane < 15) bufB[8 + lane] = softt(bufB[8 + lane], t);
        __syncwarp();
        // synthesis l6..l4: a7(bufB+8) -> bufA -> bufB -> bufA
        idwt_level<32>(bufB + 8, dbuf + doff[6], bufA, ns[7] - 3, lane);
        __syncwarp();
        idwt_level<32>(bufA, dbuf + doff[5], bufB, ns[6] - 3, lane);
        __syncwarp();
        idwt_level<32>(bufB, dbuf + doff[4], bufA, ns[5] - 3, lane);
    }
    __syncthreads();   // rejoin: a4-recon (len 76) in bufA at offset 0

    // ----- Synthesis l3..l0 (full block) -----
    idwt_level<128>(bufA, dbuf + doff[3], bufB, ns[4] - 3, tid);
    __syncthreads();
    idwt_level<128>(bufB, dbuf + doff[2], bufA, ns[3] - 3, tid);
    __syncthreads();
    idwt_level<128>(bufA, dbuf + doff[1], bufB, ns[2] - 3, tid);
    __syncthreads();
    idwt_level<128>(bufB, dbuf + doff[0], bufA, ns[1] - 3, tid);
    __syncthreads();

    // recon row = bufA[0..1115]
    {
        float4* out = (float4*)(recon + (size_t)row * NLEN);
        const float4* a4 = (const float4*)bufA;
        for (int i = tid; i < 279; i += 128) out[i] = a4[i];
    }
}

// ---------------------------------------------------------------------------
// W1 split precompute: hi/lo bf16 panels [35][112][32] (n padded to 112,
// k padded to 1120), k-panel-major so GEMM copies are contiguous uint4s.
// ---------------------------------------------------------------------------
#define KP2  35
#define NPAD 112
#define BTOT (KP2 * NPAD * 32)
__device__ __nv_bfloat16 g_Bhi[BTOT];
__device__ __nv_bfloat16 g_Blo[BTOT];

__global__ __launch_bounds__(256) void w1_split_kernel(const float* __restrict__ W1)
{
    int i = blockIdx.x * 256 + threadIdx.x;
    if (i >= BTOT) return;
    int kk = i & 31;
    int n  = (i >> 5) % NPAD;
    int p  = i / (NPAD * 32);
    int k  = p * 32 + kk;
    float v = (n < HDIM && k < NLEN) ? W1[(size_t)n * NLEN + k] : 0.0f;
    __nv_bfloat16 h = __float2bfloat16(v);
    g_Bhi[i] = h;
    g_Blo[i] = __float2bfloat16(v - __bfloat162float(h));
}

// ---------------------------------------------------------------------------
// Kernel 2: wmma bf16 GEMM (3-term split) + fused sigmoid/W2 reduction.
// Block: 128 rows x 112 cols, BK=32 (35 panels), 512 threads = 16 warps
// (8 m-tiles x 2 n-halves). DOUBLE-BUFFERED smem stages -> 1 barrier/panel.
// D = Ahi*Bhi + Ahi*Blo + Alo*Bhi  (fp32 accum; alo*blo dropped)
// ---------------------------------------------------------------------------
#define GBM 128
#define GTHREADS 512
#define ALD 40      // A smem ld (elements)
#define BLD 40      // B smem ld (elements, stride between n columns)
#define ELD 120     // epilogue smem ld (floats)
#define STG 38400   // bytes per stage: A hi/lo 2*10240 + B hi/lo 2*8960
#define GEMM_SMEM (2 * STG)    // 76800; epilogue 128*120*4=61440 fits inside

__device__ __forceinline__ void store_a_panel(char* stage, int o,
                                              float4 va0, float4 va1)
{
    __nv_bfloat16* Ahi = (__nv_bfloat16*)stage;
    __nv_bfloat16* Alo = (__nv_bfloat16*)(stage + 10240);
    __nv_bfloat16 h0 = __float2bfloat16(va0.x), h1 = __float2bfloat16(va0.y);
    __nv_bfloat16 h2 = __float2bfloat16(va0.z), h3 = __float2bfloat16(va0.w);
    __nv_bfloat16 h4 = __float2bfloat16(va1.x), h5 = __float2bfloat16(va1.y);
    __nv_bfloat16 h6 = __float2bfloat16(va1.z), h7 = __float2bfloat16(va1.w);
    __nv_bfloat162 hp0(h0, h1), hp1(h2, h3), hp2(h4, h5), hp3(h6, h7);
    __nv_bfloat162 lp0(__float2bfloat16(va0.x - __bfloat162float(h0)),
                       __float2bfloat16(va0.y - __bfloat162float(h1)));
    __nv_bfloat162 lp1(__float2bfloat16(va0.z - __bfloat162float(h2)),
                       __float2bfloat16(va0.w - __bfloat162float(h3)));
    __nv_bfloat162 lp2(__float2bfloat16(va1.x - __bfloat162float(h4)),
                       __float2bfloat16(va1.y - __bfloat162float(h5)));
    __nv_bfloat162 lp3(__float2bfloat16(va1.z - __bfloat162float(h6)),
                       __float2bfloat16(va1.w - __bfloat162float(h7)));
    *(uint4*)(Ahi + o) = make_uint4(*(uint32_t*)&hp0, *(uint32_t*)&hp1,
                                    *(uint32_t*)&hp2, *(uint32_t*)&hp3);
    *(uint4*)(Alo + o) = make_uint4(*(uint32_t*)&lp0, *(uint32_t*)&lp1,
                                    *(uint32_t*)&lp2, *(uint32_t*)&lp3);
}

__global__ __launch_bounds__(GTHREADS) void mlp_wmma_kernel(
    const float* __restrict__ recon,
    const float* __restrict__ b1,
    const float* __restrict__ W2,
    const float* __restrict__ b2,
    float* __restrict__ reg)
{
    extern __shared__ __align__(16) char smem[];
    __shared__ float b1s[NPAD];
    __shared__ float w2s[NPAD];

    float* eps = (float*)smem;    // epilogue view [128][120]

    const int tid = threadIdx.x;
    const int wid = tid >> 5;
    const int wm = wid >> 1;      // m-tile 0..7
    const int wn = wid & 1;       // n-half 0..1
    const int NT = wn ? 3 : 4;    // tiles in this half (cols 0..63 / 64..111)
    const int row0 = blockIdx.x * GBM;

    if (tid < NPAD) {
        b1s[tid] = (tid < HDIM) ? b1[tid] : 0.0f;
        w2s[tid] = (tid < HDIM) ? W2[tid] : 0.0f;
    }

    wmma::fragment<wmma::accumulator, 16, 16, 16, float> acc[4];
#pragma unroll
    for (int nt = 0; nt < 4; ++nt) wmma::fill_fragment(acc[nt], 0.0f);

    const int r = tid >> 2;       // 0..127 : A row this thread loads
    const int q = tid & 3;        // 0..3   : which 8-float chunk of the 32-k panel
    const int bj = tid;           // B copy index (tid < 448 active)
    const int ao = r * ALD + q * 8;
    const int bn = bj >> 2, bkq = bj & 3;
    const int bo = (bn * BLD + bkq * 8) * 2;

    const float* arow = recon + (size_t)(row0 + r) * NLEN + q * 8;

    // ---- stage 0: load + store panel 0
    {
        float4 va0 = *(const float4*)(arow);
        float4 va1 = *(const float4*)(arow + 4);
        store_a_panel(smem, ao, va0, va1);
        if (bj < 448) {
            *(uint4*)(smem + 20480 + bo) = ((const uint4*)g_Bhi)[bj];
            *(uint4*)(smem + 29440 + bo) = ((const uint4*)g_Blo)[bj];
        }
    }
    __syncthreads();

    for (int p = 0; p < KP2; ++p) {
        char* stage = smem + (p & 1) * STG;
        char* nstage = smem + ((p + 1) & 1) * STG;
        const bool more = (p + 1 < KP2);

        // ---- prefetch next panel (LDGs issue now, consumed after MMAs)
        float4 va0, va1;
        uint4 vbh, vbl;
        if (more) {
            const float* src = arow + (p + 1) * 32;
            va0 = *(const float4*)(src);
            if (p + 1 == KP2 - 1 && q == 3) va1 = make_float4(0.f, 0.f, 0.f, 0.f);
            else                            va1 = *(const float4*)(src + 4);
            if (bj < 448) {
                vbh = ((const uint4*)g_Bhi)[(p + 1) * 448 + bj];
                vbl = ((const uint4*)g_Blo)[(p + 1) * 448 + bj];
            }
        }

        // ---- MMAs on current stage: 2 k-steps of 16
        __nv_bfloat16* Ahi = (__nv_bfloat16*)stage;
        __nv_bfloat16* Alo = (__nv_bfloat16*)(stage + 10240);
        __nv_bfloat16* Bhi = (__nv_bfloat16*)(stage + 20480);
        __nv_bfloat16* Blo = (__nv_bfloat16*)(stage + 29440);
#pragma unroll
        for (int ks = 0; ks < 2; ++ks) {
            wmma::fragment<wmma::matrix_a, 16, 16, 16, __nv_bfloat16, wmma::row_major> fa_hi, fa_lo;
            wmma::load_matrix_sync(fa_hi, Ahi + wm * 16 * ALD + ks * 16, ALD);
            wmma::load_matrix_sync(fa_lo, Alo + wm * 16 * ALD + ks * 16, ALD);
#pragma unroll
            for (int nt = 0; nt < 4; ++nt) {
                if (nt < NT) {
                    const int n0 = (wn * 4 + nt) * 16;
                    wmma::fragment<wmma::matrix_b, 16, 16, 16, __nv_bfloat16, wmma::col_major> fb_hi, fb_lo;
                    wmma::load_matrix_sync(fb_hi, Bhi + n0 * BLD + ks * 16, BLD);
                    wmma::load_matrix_sync(fb_lo, Blo + n0 * BLD + ks * 16, BLD);
                    wmma::mma_sync(acc[nt], fa_hi, fb_hi, acc[nt]);
                    wmma::mma_sync(acc[nt], fa_hi, fb_lo, acc[nt]);
                    wmma::mma_sync(acc[nt], fa_lo, fb_hi, acc[nt]);
                }
            }
        }

        // ---- store next panel into the other stage (no reader conflict)
        if (more) {
            store_a_panel(nstage, ao, va0, va1);
            if (bj < 448) {
                *(uint4*)(nstage + 20480 + bo) = vbh;
                *(uint4*)(nstage + 29440 + bo) = vbl;
            }
        }
        __syncthreads();
    }

    // ---- epilogue: dump accumulators, sigmoid + W2 reduce
#pragma unroll
    for (int nt = 0; nt < 4; ++nt) {
        if (nt < NT) {
            wmma::store_matrix_sync(eps + wm * 16 * ELD + (wn * 4 + nt) * 16,
                                    acc[nt], ELD, wmma::mem_row_major);
        }
    }
    __syncthreads();

    {
        const float* er = eps + r * ELD;
        float s = 0.0f;
        const int c0 = q * 28;
#pragma unroll
        for (int c = 0; c < 28; ++c) {
            float pre = er[c0 + c] + b1s[c0 + c];
            float h = 1.0f / (1.0f + __expf(-pre));
            s = fmaf(h, w2s[c0 + c], s);   // w2s==0 beyond HDIM
        }
        s += __shfl_xor_sync(0xFFFFFFFFu, s, 1);
        s += __shfl_xor_sync(0xFFFFFFFFu, s, 2);
        if (q == 0) reg[row0 + r] = s + b2[0];
    }
}

// ---------------------------------------------------------------------------
extern "C" void kernel_launch(void* const* d_in, const int* in_sizes, int n_in,
                              void* d_out, int out_size)
{
    const float* x   = (const float*)d_in[0];
    const float* thr = (const float*)d_in[1];
    const float* W1  = (const float*)d_in[2];
    const float* b1  = (const float*)d_in[3];
    const float* W2  = (const float*)d_in[4];
    const float* b2  = (const float*)d_in[5];

    float* recon = (float*)d_out;
    float* reg   = (float*)d_out + (size_t)BATCH * NLEN;

    cudaFuncSetAttribute(mlp_wmma_kernel,
                         cudaFuncAttributeMaxDynamicSharedMemorySize, GEMM_SMEM);

    w1_split_kernel<<<(BTOT + 255) / 256, 256>>>(W1);
    wavelet_kernel<<<BATCH, 128>>>(x, thr, recon);
    mlp_wmma_kernel<<<BATCH / GBM, GTHREADS, GEMM_SMEM>>>(recon, b1, W2, b2, reg);
}

// round 10
// speedup vs baseline: 1.0706x; 1.0706x over previous
#include <cuda_runtime.h>
#include <cuda_bf16.h>
#include <mma.h>
#include <cstdint>
#include <math.h>

using namespace nvcuda;

#define BATCH 32768
#define NLEN  1116
#define HDIM  100

// ---------------------------------------------------------------------------
// sym4 filters
// ---------------------------------------------------------------------------
__constant__ float c_LO[8] = {
    -0.010597401784997278f,  0.032883011666982945f,  0.030841381835986965f,
    -0.18703481171888114f,  -0.02798376941698385f,   0.6308807679295904f,
     0.7148465705525415f,    0.23037781330885523f};
__constant__ float c_HI[8] = {
    -0.23037781330885523f,   0.7148465705525415f,   -0.6308807679295904f,
    -0.02798376941698385f,   0.18703481171888114f,   0.030841381835986965f,
    -0.032883011666982945f, -0.010597401784997278f};

__device__ __forceinline__ float softt(float v, float t) {
    float av = fabsf(v);
    return (av > t) ? copysignf(av - t, v) : 0.0f;
}

// One DWT level: T threads, id in [0,T); input cur (data at +8, xp[i]==cur[2+i]),
// outputs: approx -> nxt[8..], thresholded detail -> dd[0..m)
template <int T>
__device__ __forceinline__ void dwt_level(const float* cur, float* nxt, float* dd,
                                          int m, int id, float t)
{
    const int chunk = ((m + T - 1) / T) | 1;   // odd -> <=2-way LDS conflicts
    const int j0 = id * chunk;
    const int je = (j0 + chunk < m) ? (j0 + chunk) : m;
    if (j0 < je) {
        const float* p = cur + 2 + 2 * j0;
        float w0 = p[0], w1 = p[1], w2 = p[2], w3 = p[3];
        float w4 = p[4], w5 = p[5], w6 = p[6], w7 = p[7];
        int idx = 8;
        for (int j = j0; j < je; ++j) {
            float lo = w0 * c_LO[7];
            lo = fmaf(w1, c_LO[6], lo); lo = fmaf(w2, c_LO[5], lo);
            lo = fmaf(w3, c_LO[4], lo); lo = fmaf(w4, c_LO[3], lo);
            lo = fmaf(w5, c_LO[2], lo); lo = fmaf(w6, c_LO[1], lo);
            lo = fmaf(w7, c_LO[0], lo);
            float hi = w0 * c_HI[7];
            hi = fmaf(w1, c_HI[6], hi); hi = fmaf(w2, c_HI[5], hi);
            hi = fmaf(w3, c_HI[4], hi); hi = fmaf(w4, c_HI[3], hi);
            hi = fmaf(w5, c_HI[2], hi); hi = fmaf(w6, c_HI[1], hi);
            hi = fmaf(w7, c_HI[0], hi);
            nxt[8 + j] = lo;
            dd[j] = softt(hi, t);
            w0 = w2; w1 = w3; w2 = w4; w3 = w5; w4 = w6; w5 = w7;
            float2 nx = *(const float2*)(p + idx);   // 8B-aligned (even offset)
            w6 = nx.x; w7 = nx.y; idx += 2;          // lookahead (array slack)
        }
    }
    if (id < 6) nxt[2 + id] = 0.0f;
    if (id < 8) nxt[8 + m + id] = 0.0f;
}

// One IDWT level: a at abase[0..], d at dd[0..], output pairs to obase.
template <int T>
__device__ __forceinline__ void idwt_level(const float* abase, const float* dd,
                                           float* obase, int pairs, int id)
{
    const int chunk = ((pairs + T - 1) / T) | 1;
    const int p0 = id * chunk;
    const int pe = (p0 + chunk < pairs) ? (p0 + chunk) : pairs;
    if (p0 < pe) {
        float a0 = abase[p0], a1 = abase[p0 + 1], a2 = abase[p0 + 2], a3 = abase[p0 + 3];
        float d0 = dd[p0],    d1 = dd[p0 + 1],    d2 = dd[p0 + 2],    d3 = dd[p0 + 3];
        for (int p = p0; p < pe; ++p) {
            float ye = a0 * c_LO[1];
            ye = fmaf(a1, c_LO[3], ye); ye = fmaf(a2, c_LO[5], ye); ye = fmaf(a3, c_LO[7], ye);
            ye = fmaf(d0, c_HI[1], ye); ye = fmaf(d1, c_HI[3], ye);
            ye = fmaf(d2, c_HI[5], ye); ye = fmaf(d3, c_HI[7], ye);
            float yo = a0 * c_LO[0];
            yo = fmaf(a1, c_LO[2], yo); yo = fmaf(a2, c_LO[4], yo); yo = fmaf(a3, c_LO[6], yo);
            yo = fmaf(d0, c_HI[0], yo); yo = fmaf(d1, c_HI[2], yo);
            yo = fmaf(d2, c_HI[4], yo); yo = fmaf(d3, c_HI[6], yo);
            ((float2*)obase)[p] = make_float2(ye, yo);
            a0 = a1; a1 = a2; a2 = a3; a3 = abase[p + 4];   // lookahead ok
            d0 = d1; d1 = d2; d2 = d3; d3 = dd[p + 4];
        }
    }
}

// ---------------------------------------------------------------------------
// Kernel 1: per-row 7-level DWT -> soft threshold -> IDWT.
// One 128-thread block per row. Shallow levels: full block + barrier.
// Deep levels (analysis l3-l6, soft, synthesis l6-l4): warp 0 only with
// __syncwarp; other warps sleep at one rejoin barrier.
// Levels: 1116 -> 561 -> 284 -> 145 -> 76 -> 41 -> 24 -> 15
// ---------------------------------------------------------------------------
__global__ __launch_bounds__(128) void wavelet_kernel(
    const float* __restrict__ x,
    const float* __restrict__ thr,
    float* __restrict__ recon)
{
    __shared__ __align__(16) float bufA[1140];
    __shared__ __align__(16) float bufB[1140];
    __shared__ __align__(16) float dbuf[1152];

    const int tid = threadIdx.x;
    const int row = blockIdx.x;
    const float t = fmaxf(thr[0], 0.01f);

    const int ns[8]   = {1116, 561, 284, 145, 76, 41, 24, 15};
    const int doff[7] = {0, 561, 845, 990, 1066, 1107, 1131};

    // Load row (vectorized): 1116 = 279 float4
    {
        const float4* xr = (const float4*)(x + (size_t)row * NLEN);
        float4* dst = (float4*)(bufA + 8);
        for (int i = tid; i < 279; i += 128) dst[i] = xr[i];
        if (tid < 6) bufA[2 + tid] = 0.0f;
        if (tid < 8) bufA[8 + NLEN + tid] = 0.0f;
    }
    __syncthreads();

    // ----- Analysis l0..l2 (full block) -----
    dwt_level<128>(bufA, bufB, dbuf + doff[0], ns[1], tid, t);
    __syncthreads();
    dwt_level<128>(bufB, bufA, dbuf + doff[1], ns[2], tid, t);
    __syncthreads();
    dwt_level<128>(bufA, bufB, dbuf + doff[2], ns[3], tid, t);
    __syncthreads();

    // ----- Deep phase: warp 0 only -----
    if (tid < 32) {
        const int lane = tid;
        // analysis l3..l6: bufB->bufA->bufB->bufA->bufB (a7 in bufB at +8)
        dwt_level<32>(bufB, bufA, dbuf + doff[3], ns[4], lane, t);
        __syncwarp();
        dwt_level<32>(bufA, bufB, dbuf + doff[4], ns[5], lane, t);
        __syncwarp();
        dwt_level<32>(bufB, bufA, dbuf + doff[5], ns[6], lane, t);
        __syncwarp();
        dwt_level<32>(bufA, bufB, dbuf + doff[6], ns[7], lane, t);
        __syncwarp();
        // soft-threshold final approx (len 15)
        if (lane < 15) bufB[8 + lane] = softt(bufB[8 + lane], t);
        __syncwarp();
        // synthesis l6..l4: a7(bufB+8) -> bufA -> bufB -> bufA
        idwt_level<32>(bufB + 8, dbuf + doff[6], bufA, ns[7] - 3, lane);
        __syncwarp();
        idwt_level<32>(bufA, dbuf + doff[5], bufB, ns[6] - 3, lane);
        __syncwarp();
        idwt_level<32>(bufB, dbuf + doff[4], bufA, ns[5] - 3, lane);
    }
    __syncthreads();   // rejoin: a4-recon (len 76) in bufA at offset 0

    // ----- Synthesis l3..l0 (full block) -----
    idwt_level<128>(bufA, dbuf + doff[3], bufB, ns[4] - 3, tid);
    __syncthreads();
    idwt_level<128>(bufB, dbuf + doff[2], bufA, ns[3] - 3, tid);
    __syncthreads();
    idwt_level<128>(bufA, dbuf + doff[1], bufB, ns[2] - 3, tid);
    __syncthreads();
    idwt_level<128>(bufB, dbuf + doff[0], bufA, ns[1] - 3, tid);
    __syncthreads();

    // recon row = bufA[0..1115]
    {
        float4* out = (float4*)(recon + (size_t)row * NLEN);
        const float4* a4 = (const float4*)bufA;
        for (int i = tid; i < 279; i += 128) out[i] = a4[i];
    }
}

// ---------------------------------------------------------------------------
// W1 split precompute: hi/lo bf16 panels [35][112][32] (n padded to 112,
// k padded to 1120), k-panel-major so GEMM copies are contiguous uint4s.
// ---------------------------------------------------------------------------
#define KP2  35
#define NPAD 112
#define BTOT (KP2 * NPAD * 32)
__device__ __nv_bfloat16 g_Bhi[BTOT];
__device__ __nv_bfloat16 g_Blo[BTOT];

__global__ __launch_bounds__(256) void w1_split_kernel(const float* __restrict__ W1)
{
    int i = blockIdx.x * 256 + threadIdx.x;
    if (i >= BTOT) return;
    int kk = i & 31;
    int n  = (i >> 5) % NPAD;
    int p  = i / (NPAD * 32);
    int k  = p * 32 + kk;
    float v = (n < HDIM && k < NLEN) ? W1[(size_t)n * NLEN + k] : 0.0f;
    __nv_bfloat16 h = __float2bfloat16(v);
    g_Bhi[i] = h;
    g_Blo[i] = __float2bfloat16(v - __bfloat162float(h));
}

// ---------------------------------------------------------------------------
// Kernel 2: wmma bf16 GEMM (3-term split) + fused sigmoid/W2 reduction.
// EXACT R8 structure (single-stage, 2 barriers/panel, register prefetch of
// next A panel from GMEM and next B panel from L2).
// Block: 128 rows x 112 cols, BK=32 (35 panels), 512 threads = 16 warps.
// D = Ahi*Bhi + Ahi*Blo + Alo*Bhi  (fp32 accum; alo*blo dropped)
// ---------------------------------------------------------------------------
#define GBM 128
#define GTHREADS 512
#define ALD 40      // A smem ld (elements)
#define BLD 40      // B smem ld (elements, stride between n columns)
#define ELD 120     // epilogue smem ld (floats)
// dynamic smem: union( A(20480)+B(17920)=38400 , eps 128*120*4=61440 )
#define GEMM_SMEM (GBM * ELD * 4)

__global__ __launch_bounds__(GTHREADS) void mlp_wmma_kernel(
    const float* __restrict__ recon,
    const float* __restrict__ b1,
    const float* __restrict__ W2,
    const float* __restrict__ b2,
    float* __restrict__ reg)
{
    extern __shared__ __align__(16) char smem[];
    __shared__ float b1s[NPAD];
    __shared__ float w2s[NPAD];

    __nv_bfloat16* Ahi = (__nv_bfloat16*)(smem);              // [128][40] 10240 B
    __nv_bfloat16* Alo = (__nv_bfloat16*)(smem + 10240);      // [128][40] 10240 B
    char* BhiB = smem + 20480;                                 // [112][40]  8960 B
    char* BloB = smem + 29440;                                 // [112][40]  8960 B
    float* eps = (float*)smem;                                 // [128][120]

    const int tid = threadIdx.x;
    const int wid = tid >> 5;
    const int wm = wid >> 1;      // m-tile 0..7
    const int wn = wid & 1;       // n-half 0..1
    const int NT = wn ? 3 : 4;    // tiles in this half (cols 0..63 / 64..111)
    const int row0 = blockIdx.x * GBM;

    if (tid < NPAD) {
        b1s[tid] = (tid < HDIM) ? b1[tid] : 0.0f;
        w2s[tid] = (tid < HDIM) ? W2[tid] : 0.0f;
    }

    wmma::fragment<wmma::accumulator, 16, 16, 16, float> acc[4];
#pragma unroll
    for (int nt = 0; nt < 4; ++nt) wmma::fill_fragment(acc[nt], 0.0f);

    const int r = tid >> 2;       // 0..127 : A row this thread loads
    const int q = tid & 3;        // 0..3   : which 8-float chunk of the 32-k panel
    const int bj = tid;           // B copy index (tid < 448 active)

    // --- prefetch registers
    float4 va0, va1;
    uint4 vbh0, vbl0;
    const float* arow = recon + (size_t)(row0 + r) * NLEN + q * 8;
    {   // panel 0 (always full)
        va0 = *(const float4*)(arow);
        va1 = *(const float4*)(arow + 4);
        if (bj < 448) {
            vbh0 = ((const uint4*)g_Bhi)[bj];
            vbl0 = ((const uint4*)g_Blo)[bj];
        }
    }

    for (int p = 0; p < KP2; ++p) {
        // ---- convert & store A panel p from registers
        {
            __nv_bfloat16 h0 = __float2bfloat16(va0.x), h1 = __float2bfloat16(va0.y);
            __nv_bfloat16 h2 = __float2bfloat16(va0.z), h3 = __float2bfloat16(va0.w);
            __nv_bfloat16 h4 = __float2bfloat16(va1.x), h5 = __float2bfloat16(va1.y);
            __nv_bfloat16 h6 = __float2bfloat16(va1.z), h7 = __float2bfloat16(va1.w);
            __nv_bfloat162 hp0(h0, h1), hp1(h2, h3), hp2(h4, h5), hp3(h6, h7);
            __nv_bfloat162 lp0(__float2bfloat16(va0.x - __bfloat162float(h0)),
                               __float2bfloat16(va0.y - __bfloat162float(h1)));
            __nv_bfloat162 lp1(__float2bfloat16(va0.z - __bfloat162float(h2)),
                               __float2bfloat16(va0.w - __bfloat162float(h3)));
            __nv_bfloat162 lp2(__float2bfloat16(va1.x - __bfloat162float(h4)),
                               __float2bfloat16(va1.y - __bfloat162float(h5)));
            __nv_bfloat162 lp3(__float2bfloat16(va1.z - __bfloat162float(h6)),
                               __float2bfloat16(va1.w - __bfloat162float(h7)));
            const int o = r * ALD + q * 8;       // element offset (16B aligned)
            *(uint4*)(Ahi + o) = make_uint4(*(uint32_t*)&hp0, *(uint32_t*)&hp1,
                                            *(uint32_t*)&hp2, *(uint32_t*)&hp3);
            *(uint4*)(Alo + o) = make_uint4(*(uint32_t*)&lp0, *(uint32_t*)&lp1,
                                            *(uint32_t*)&lp2, *(uint32_t*)&lp3);
        }
        // ---- store B panel p from registers
        if (bj < 448) {
            const int n = bj >> 2, kq = bj & 3;
            *(uint4*)(BhiB + (n * BLD + kq * 8) * 2) = vbh0;
            *(uint4*)(BloB + (n * BLD + kq * 8) * 2) = vbl0;
        }
        __syncthreads();

        // ---- prefetch next panel (A from GMEM, B from L2) while MMAs run
        if (p + 1 < KP2) {
            const float* src = arow + (p + 1) * 32;
            if (p + 1 == KP2 - 1 && q == 3) {          // k = 1112..1119: last 4 pad
                va0 = *(const float4*)(src);
                va1 = make_float4(0.f, 0.f, 0.f, 0.f);
            } else {
                va0 = *(const float4*)(src);
                va1 = *(const float4*)(src + 4);
            }
            if (bj < 448) {
                vbh0 = ((const uint4*)g_Bhi)[(p + 1) * 448 + bj];
                vbl0 = ((const uint4*)g_Blo)[(p + 1) * 448 + bj];
            }
        }

        // ---- MMAs: 2 k-steps of 16
#pragma unroll
        for (int ks = 0; ks < 2; ++ks) {
            wmma::fragment<wmma::matrix_a, 16, 16, 16, __nv_bfloat16, wmma::row_major> fa_hi, fa_lo;
            wmma::load_matrix_sync(fa_hi, Ahi + wm * 16 * ALD + ks * 16, ALD);
            wmma::load_matrix_sync(fa_lo, Alo + wm * 16 * ALD + ks * 16, ALD);
#pragma unroll
            for (int nt = 0; nt < 4; ++nt) {
                if (nt < NT) {
                    const int n0 = (wn * 4 + nt) * 16;
                    wmma::fragment<wmma::matrix_b, 16, 16, 16, __nv_bfloat16, wmma::col_major> fb_hi, fb_lo;
                    wmma::load_matrix_sync(fb_hi, (__nv_bfloat16*)BhiB + n0 * BLD + ks * 16, BLD);
                    wmma::load_matrix_sync(fb_lo, (__nv_bfloat16*)BloB + n0 * BLD + ks * 16, BLD);
                    wmma::mma_sync(acc[nt], fa_hi, fb_hi, acc[nt]);
                    wmma::mma_sync(acc[nt], fa_hi, fb_lo, acc[nt]);
                    wmma::mma_sync(acc[nt], fa_lo, fb_hi, acc[nt]);
                }
            }
        }
        __syncthreads();
    }

    // ---- epilogue: dump accumulators, sigmoid + W2 reduce
#pragma unroll
    for (int nt = 0; nt < 4; ++nt) {
        if (nt < NT) {
            wmma::store_matrix_sync(eps + wm * 16 * ELD + (wn * 4 + nt) * 16,
                                    acc[nt], ELD, wmma::mem_row_major);
        }
    }
    __syncthreads();

    {
        const float* er = eps + r * ELD;
        float s = 0.0f;
        const int c0 = q * 28;
#pragma unroll
        for (int c = 0; c < 28; ++c) {
            float pre = er[c0 + c] + b1s[c0 + c];
            float h = 1.0f / (1.0f + __expf(-pre));
            s = fmaf(h, w2s[c0 + c], s);   // w2s==0 beyond HDIM
        }
        s += __shfl_xor_sync(0xFFFFFFFFu, s, 1);
        s += __shfl_xor_sync(0xFFFFFFFFu, s, 2);
        if (q == 0) reg[row0 + r] = s + b2[0];
    }
}

// ---------------------------------------------------------------------------
// Launch order: wavelet FIRST (so the ncu -s/-c capture slot that has been
// landing on w1_split lands on wavelet next round), then w1_split, then mlp.
// mlp depends on both; w1_split and wavelet are independent.
// ---------------------------------------------------------------------------
extern "C" void kernel_launch(void* const* d_in, const int* in_sizes, int n_in,
                              void* d_out, int out_size)
{
    const float* x   = (const float*)d_in[0];
    const float* thr = (const float*)d_in[1];
    const float* W1  = (const float*)d_in[2];
    const float* b1  = (const float*)d_in[3];
    const float* W2  = (const float*)d_in[4];
    const float* b2  = (const float*)d_in[5];

    float* recon = (float*)d_out;
    float* reg   = (float*)d_out + (size_t)BATCH * NLEN;

    cudaFuncSetAttribute(mlp_wmma_kernel,
                         cudaFuncAttributeMaxDynamicSharedMemorySize, GEMM_SMEM);

    wavelet_kernel<<<BATCH, 128>>>(x, thr, recon);
    w1_split_kernel<<<(BTOT + 255) / 256, 256>>>(W1);
    mlp_wmma_kernel<<<BATCH / GBM, GTHREADS, GEMM_SMEM>>>(recon, b1, W2, b2, reg);
}

// round 11
// speedup vs baseline: 1.3320x; 1.2441x over previous
#include <cuda_runtime.h>
#include <cuda_bf16.h>
#include <mma.h>
#include <cstdint>
#include <math.h>

using namespace nvcuda;

#define BATCH 32768
#define NLEN  1116
#define HDIM  100

// ---------------------------------------------------------------------------
// sym4 filters
// ---------------------------------------------------------------------------
__constant__ float c_LO[8] = {
    -0.010597401784997278f,  0.032883011666982945f,  0.030841381835986965f,
    -0.18703481171888114f,  -0.02798376941698385f,   0.6308807679295904f,
     0.7148465705525415f,    0.23037781330885523f};
__constant__ float c_HI[8] = {
    -0.23037781330885523f,   0.7148465705525415f,   -0.6308807679295904f,
    -0.02798376941698385f,   0.18703481171888114f,   0.030841381835986965f,
    -0.032883011666982945f, -0.010597401784997278f};

__device__ __forceinline__ float softt(float v, float t) {
    float av = fabsf(v);
    return (av > t) ? copysignf(av - t, v) : 0.0f;
}

// One DWT level, COMPILE-TIME size M, T threads. Fully unrolled inner loop:
// register windows rotate via renaming (no MOVs), LDS offsets are immediates.
template <int T, int M>
__device__ __forceinline__ void dwt_level(const float* cur, float* nxt, float* dd,
                                          int id, float t)
{
    constexpr int CH = ((M + T - 1) / T) | 1;   // odd -> <=2-way LDS conflicts
    const int j0 = id * CH;
    if (j0 < M) {
        const float* p = cur + 2 + 2 * j0;
        float w0 = p[0], w1 = p[1], w2 = p[2], w3 = p[3];
        float w4 = p[4], w5 = p[5], w6 = p[6], w7 = p[7];
#pragma unroll
        for (int jj = 0; jj < CH; ++jj) {
            const int j = j0 + jj;
            float lo = w0 * c_LO[7];
            lo = fmaf(w1, c_LO[6], lo); lo = fmaf(w2, c_LO[5], lo);
            lo = fmaf(w3, c_LO[4], lo); lo = fmaf(w4, c_LO[3], lo);
            lo = fmaf(w5, c_LO[2], lo); lo = fmaf(w6, c_LO[1], lo);
            lo = fmaf(w7, c_LO[0], lo);
            float hi = w0 * c_HI[7];
            hi = fmaf(w1, c_HI[6], hi); hi = fmaf(w2, c_HI[5], hi);
            hi = fmaf(w3, c_HI[4], hi); hi = fmaf(w4, c_HI[3], hi);
            hi = fmaf(w5, c_HI[2], hi); hi = fmaf(w6, c_HI[1], hi);
            hi = fmaf(w7, c_HI[0], hi);
            if (j < M) {
                nxt[8 + j] = lo;
                dd[j] = softt(hi, t);
            }
            if (jj + 1 < CH) {
                w0 = w2; w1 = w3; w2 = w4; w3 = w5; w4 = w6; w5 = w7;
                float2 nx = *(const float2*)(p + 8 + 2 * jj);   // immediate offset
                w6 = nx.x; w7 = nx.y;                            // lookahead slack ok
            }
        }
    }
    if (id < 6) nxt[2 + id] = 0.0f;
    if (id < 8) nxt[8 + M + id] = 0.0f;
}

// One IDWT level, COMPILE-TIME pair count P.
template <int T, int P>
__device__ __forceinline__ void idwt_level(const float* abase, const float* dd,
                                           float* obase, int id)
{
    constexpr int CH = ((P + T - 1) / T) | 1;
    const int p0 = id * CH;
    if (p0 < P) {
        float a0 = abase[p0], a1 = abase[p0 + 1], a2 = abase[p0 + 2], a3 = abase[p0 + 3];
        float d0 = dd[p0],    d1 = dd[p0 + 1],    d2 = dd[p0 + 2],    d3 = dd[p0 + 3];
#pragma unroll
        for (int jj = 0; jj < CH; ++jj) {
            const int p = p0 + jj;
            float ye = a0 * c_LO[1];
            ye = fmaf(a1, c_LO[3], ye); ye = fmaf(a2, c_LO[5], ye); ye = fmaf(a3, c_LO[7], ye);
            ye = fmaf(d0, c_HI[1], ye); ye = fmaf(d1, c_HI[3], ye);
            ye = fmaf(d2, c_HI[5], ye); ye = fmaf(d3, c_HI[7], ye);
            float yo = a0 * c_LO[0];
            yo = fmaf(a1, c_LO[2], yo); yo = fmaf(a2, c_LO[4], yo); yo = fmaf(a3, c_LO[6], yo);
            yo = fmaf(d0, c_HI[0], yo); yo = fmaf(d1, c_HI[2], yo);
            yo = fmaf(d2, c_HI[4], yo); yo = fmaf(d3, c_HI[6], yo);
            if (p < P) ((float2*)obase)[p] = make_float2(ye, yo);
            if (jj + 1 < CH) {
                a0 = a1; a1 = a2; a2 = a3; a3 = abase[p0 + jj + 4];   // lookahead ok
                d0 = d1; d1 = d2; d2 = d3; d3 = dd[p0 + jj + 4];
            }
        }
    }
}

// ---------------------------------------------------------------------------
// Kernel 1: per-row 7-level DWT -> soft threshold -> IDWT.
// One 128-thread block per row. Shallow levels: full block + barrier.
// Deep levels: warp 0 only with __syncwarp; others sleep at rejoin barrier.
// Levels: 1116 -> 561 -> 284 -> 145 -> 76 -> 41 -> 24 -> 15
// Detail offsets: 0, 561, 845, 990, 1066, 1107, 1131
// ---------------------------------------------------------------------------
__global__ __launch_bounds__(128) void wavelet_kernel(
    const float* __restrict__ x,
    const float* __restrict__ thr,
    float* __restrict__ recon)
{
    __shared__ __align__(16) float bufA[1140];
    __shared__ __align__(16) float bufB[1140];
    __shared__ __align__(16) float dbuf[1152];

    const int tid = threadIdx.x;
    const int row = blockIdx.x;
    const float t = fmaxf(thr[0], 0.01f);

    // Load row (vectorized): 1116 = 279 float4
    {
        const float4* xr = (const float4*)(x + (size_t)row * NLEN);
        float4* dst = (float4*)(bufA + 8);
        for (int i = tid; i < 279; i += 128) dst[i] = xr[i];
        if (tid < 6) bufA[2 + tid] = 0.0f;
        if (tid < 8) bufA[8 + NLEN + tid] = 0.0f;
    }
    __syncthreads();

    // ----- Analysis l0..l2 (full block) -----
    dwt_level<128, 561>(bufA, bufB, dbuf + 0,   tid, t);
    __syncthreads();
    dwt_level<128, 284>(bufB, bufA, dbuf + 561, tid, t);
    __syncthreads();
    dwt_level<128, 145>(bufA, bufB, dbuf + 845, tid, t);
    __syncthreads();

    // ----- Deep phase: warp 0 only -----
    if (tid < 32) {
        const int lane = tid;
        // analysis l3..l6: bufB->bufA->bufB->bufA->bufB (a7 in bufB at +8)
        dwt_level<32, 76>(bufB, bufA, dbuf + 990,  lane, t);
        __syncwarp();
        dwt_level<32, 41>(bufA, bufB, dbuf + 1066, lane, t);
        __syncwarp();
        dwt_level<32, 24>(bufB, bufA, dbuf + 1107, lane, t);
        __syncwarp();
        dwt_level<32, 15>(bufA, bufB, dbuf + 1131, lane, t);
        __syncwarp();
        // soft-threshold final approx (len 15)
        if (lane < 15) bufB[8 + lane] = softt(bufB[8 + lane], t);
        __syncwarp();
        // synthesis l6..l4: a7(bufB+8) -> bufA -> bufB -> bufA
        idwt_level<32, 12>(bufB + 8, dbuf + 1131, bufA, lane);
        __syncwarp();
        idwt_level<32, 21>(bufA, dbuf + 1107, bufB, lane);
        __syncwarp();
        idwt_level<32, 38>(bufB, dbuf + 1066, bufA, lane);
    }
    __syncthreads();   // rejoin: a4-recon (len 76) in bufA at offset 0

    // ----- Synthesis l3..l0 (full block) -----
    idwt_level<128, 73>(bufA, dbuf + 990, bufB, tid);
    __syncthreads();
    idwt_level<128, 142>(bufB, dbuf + 845, bufA, tid);
    __syncthreads();
    idwt_level<128, 281>(bufA, dbuf + 561, bufB, tid);
    __syncthreads();
    idwt_level<128, 558>(bufB, dbuf + 0, bufA, tid);
    __syncthreads();

    // recon row = bufA[0..1115]
    {
        float4* out = (float4*)(recon + (size_t)row * NLEN);
        const float4* a4 = (const float4*)bufA;
        for (int i = tid; i < 279; i += 128) out[i] = a4[i];
    }
}

// ---------------------------------------------------------------------------
// W1 split precompute: hi/lo bf16 panels [35][112][32] (n padded to 112,
// k padded to 1120), k-panel-major so GEMM copies are contiguous uint4s.
// ---------------------------------------------------------------------------
#define KP2  35
#define NPAD 112
#define BTOT (KP2 * NPAD * 32)
__device__ __nv_bfloat16 g_Bhi[BTOT];
__device__ __nv_bfloat16 g_Blo[BTOT];

__global__ __launch_bounds__(256) void w1_split_kernel(const float* __restrict__ W1)
{
    int i = blockIdx.x * 256 + threadIdx.x;
    if (i >= BTOT) return;
    int kk = i & 31;
    int n  = (i >> 5) % NPAD;
    int p  = i / (NPAD * 32);
    int k  = p * 32 + kk;
    float v = (n < HDIM && k < NLEN) ? W1[(size_t)n * NLEN + k] : 0.0f;
    __nv_bfloat16 h = __float2bfloat16(v);
    g_Bhi[i] = h;
    g_Blo[i] = __float2bfloat16(v - __bfloat162float(h));
}

// ---------------------------------------------------------------------------
// Kernel 2: wmma bf16 GEMM (3-term split) + fused sigmoid/W2 reduction.
// R8 structure (single-stage, 2 barriers/panel, register prefetch of next
// A panel from GMEM and next B panel from L2).
// Block: 128 rows x 112 cols, BK=32 (35 panels), 512 threads = 16 warps.
// D = Ahi*Bhi + Ahi*Blo + Alo*Bhi  (fp32 accum; alo*blo dropped)
// ---------------------------------------------------------------------------
#define GBM 128
#define GTHREADS 512
#define ALD 40      // A smem ld (elements)
#define BLD 40      // B smem ld (elements, stride between n columns)
#define ELD 120     // epilogue smem ld (floats)
// dynamic smem: union( A(20480)+B(17920)=38400 , eps 128*120*4=61440 )
#define GEMM_SMEM (GBM * ELD * 4)

__global__ __launch_bounds__(GTHREADS) void mlp_wmma_kernel(
    const float* __restrict__ recon,
    const float* __restrict__ b1,
    const float* __restrict__ W2,
    const float* __restrict__ b2,
    float* __restrict__ reg)
{
    extern __shared__ __align__(16) char smem[];
    __shared__ float b1s[NPAD];
    __shared__ float w2s[NPAD];

    __nv_bfloat16* Ahi = (__nv_bfloat16*)(smem);              // [128][40] 10240 B
    __nv_bfloat16* Alo = (__nv_bfloat16*)(smem + 10240);      // [128][40] 10240 B
    char* BhiB = smem + 20480;                                 // [112][40]  8960 B
    char* BloB = smem + 29440;                                 // [112][40]  8960 B
    float* eps = (float*)smem;                                 // [128][120]

    const int tid = threadIdx.x;
    const int wid = tid >> 5;
    const int wm = wid >> 1;      // m-tile 0..7
    const int wn = wid & 1;       // n-half 0..1
    const int NT = wn ? 3 : 4;    // tiles in this half (cols 0..63 / 64..111)
    const int row0 = blockIdx.x * GBM;

    if (tid < NPAD) {
        b1s[tid] = (tid < HDIM) ? b1[tid] : 0.0f;
        w2s[tid] = (tid < HDIM) ? W2[tid] : 0.0f;
    }

    wmma::fragment<wmma::accumulator, 16, 16, 16, float> acc[4];
#pragma unroll
    for (int nt = 0; nt < 4; ++nt) wmma::fill_fragment(acc[nt], 0.0f);

    const int r = tid >> 2;       // 0..127 : A row this thread loads
    const int q = tid & 3;        // 0..3   : which 8-float chunk of the 32-k panel
    const int bj = tid;           // B copy index (tid < 448 active)

    // --- prefetch registers
    float4 va0, va1;
    uint4 vbh0, vbl0;
    const float* arow = recon + (size_t)(row0 + r) * NLEN + q * 8;
    {   // panel 0 (always full)
        va0 = *(const float4*)(arow);
        va1 = *(const float4*)(arow + 4);
        if (bj < 448) {
            vbh0 = ((const uint4*)g_Bhi)[bj];
            vbl0 = ((const uint4*)g_Blo)[bj];
        }
    }

    for (int p = 0; p < KP2; ++p) {
        // ---- convert & store A panel p from registers
        {
            __nv_bfloat16 h0 = __float2bfloat16(va0.x), h1 = __float2bfloat16(va0.y);
            __nv_bfloat16 h2 = __float2bfloat16(va0.z), h3 = __float2bfloat16(va0.w);
            __nv_bfloat16 h4 = __float2bfloat16(va1.x), h5 = __float2bfloat16(va1.y);
            __nv_bfloat16 h6 = __float2bfloat16(va1.z), h7 = __float2bfloat16(va1.w);
            __nv_bfloat162 hp0(h0, h1), hp1(h2, h3), hp2(h4, h5), hp3(h6, h7);
            __nv_bfloat162 lp0(__float2bfloat16(va0.x - __bfloat162float(h0)),
                               __float2bfloat16(va0.y - __bfloat162float(h1)));
            __nv_bfloat162 lp1(__float2bfloat16(va0.z - __bfloat162float(h2)),
                               __float2bfloat16(va0.w - __bfloat162float(h3)));
            __nv_bfloat162 lp2(__float2bfloat16(va1.x - __bfloat162float(h4)),
                               __float2bfloat16(va1.y - __bfloat162float(h5)));
            __nv_bfloat162 lp3(__float2bfloat16(va1.z - __bfloat162float(h6)),
                               __float2bfloat16(va1.w - __bfloat162float(h7)));
            const int o = r * ALD + q * 8;       // element offset (16B aligned)
            *(uint4*)(Ahi + o) = make_uint4(*(uint32_t*)&hp0, *(uint32_t*)&hp1,
                                            *(uint32_t*)&hp2, *(uint32_t*)&hp3);
            *(uint4*)(Alo + o) = make_uint4(*(uint32_t*)&lp0, *(uint32_t*)&lp1,
                                            *(uint32_t*)&lp2, *(uint32_t*)&lp3);
        }
        // ---- store B panel p from registers
        if (bj < 448) {
            const int n = bj >> 2, kq = bj & 3;
            *(uint4*)(BhiB + (n * BLD + kq * 8) * 2) = vbh0;
            *(uint4*)(BloB + (n * BLD + kq * 8) * 2) = vbl0;
        }
        __syncthreads();

        // ---- prefetch next panel (A from GMEM, B from L2) while MMAs run
        if (p + 1 < KP2) {
            const float* src = arow + (p + 1) * 32;
            if (p + 1 == KP2 - 1 && q == 3) {          // k = 1112..1119: last 4 pad
                va0 = *(const float4*)(src);
                va1 = make_float4(0.f, 0.f, 0.f, 0.f);
            } else {
                va0 = *(const float4*)(src);
                va1 = *(const float4*)(src + 4);
            }
            if (bj < 448) {
                vbh0 = ((const uint4*)g_Bhi)[(p + 1) * 448 + bj];
                vbl0 = ((const uint4*)g_Blo)[(p + 1) * 448 + bj];
            }
        }

        // ---- MMAs: 2 k-steps of 16
#pragma unroll
        for (int ks = 0; ks < 2; ++ks) {
            wmma::fragment<wmma::matrix_a, 16, 16, 16, __nv_bfloat16, wmma::row_major> fa_hi, fa_lo;
            wmma::load_matrix_sync(fa_hi, Ahi + wm * 16 * ALD + ks * 16, ALD);
            wmma::load_matrix_sync(fa_lo, Alo + wm * 16 * ALD + ks * 16, ALD);
#pragma unroll
            for (int nt = 0; nt < 4; ++nt) {
                if (nt < NT) {
                    const int n0 = (wn * 4 + nt) * 16;
                    wmma::fragment<wmma::matrix_b, 16, 16, 16, __nv_bfloat16, wmma::col_major> fb_hi, fb_lo;
                    wmma::load_matrix_sync(fb_hi, (__nv_bfloat16*)BhiB + n0 * BLD + ks * 16, BLD);
                    wmma::load_matrix_sync(fb_lo, (__nv_bfloat16*)BloB + n0 * BLD + ks * 16, BLD);
                    wmma::mma_sync(acc[nt], fa_hi, fb_hi, acc[nt]);
                    wmma::mma_sync(acc[nt], fa_hi, fb_lo, acc[nt]);
                    wmma::mma_sync(acc[nt], fa_lo, fb_hi, acc[nt]);
                }
            }
        }
        __syncthreads();
    }

    // ---- epilogue: dump accumulators, sigmoid + W2 reduce
#pragma unroll
    for (int nt = 0; nt < 4; ++nt) {
        if (nt < NT) {
            wmma::store_matrix_sync(eps + wm * 16 * ELD + (wn * 4 + nt) * 16,
                                    acc[nt], ELD, wmma::mem_row_major);
        }
    }
    __syncthreads();

    {
        const float* er = eps + r * ELD;
        float s = 0.0f;
        const int c0 = q * 28;
#pragma unroll
        for (int c = 0; c < 28; ++c) {
            float pre = er[c0 + c] + b1s[c0 + c];
            float h = 1.0f / (1.0f + __expf(-pre));
            s = fmaf(h, w2s[c0 + c], s);   // w2s==0 beyond HDIM
        }
        s += __shfl_xor_sync(0xFFFFFFFFu, s, 1);
        s += __shfl_xor_sync(0xFFFFFFFFu, s, 2);
        if (q == 0) reg[row0 + r] = s + b2[0];
    }
}

// ---------------------------------------------------------------------------
extern "C" void kernel_launch(void* const* d_in, const int* in_sizes, int n_in,
                              void* d_out, int out_size)
{
    const float* x   = (const float*)d_in[0];
    const float* thr = (const float*)d_in[1];
    const float* W1  = (const float*)d_in[2];
    const float* b1  = (const float*)d_in[3];
    const float* W2  = (const float*)d_in[4];
    const float* b2  = (const float*)d_in[5];

    float* recon = (float*)d_out;
    float* reg   = (float*)d_out + (size_t)BATCH * NLEN;

    cudaFuncSetAttribute(mlp_wmma_kernel,
                         cudaFuncAttributeMaxDynamicSharedMemorySize, GEMM_SMEM);

    wavelet_kernel<<<BATCH, 128>>>(x, thr, recon);
    w1_split_kernel<<<(BTOT + 255) / 256, 256>>>(W1);
    mlp_wmma_kernel<<<BATCH / GBM, GTHREADS, GEMM_SMEM>>>(recon, b1, W2, b2, reg);
}

// round 12
// speedup vs baseline: 1.4455x; 1.0852x over previous
#include <cuda_runtime.h>
#include <cuda_bf16.h>
#include <mma.h>
#include <cstdint>
#include <math.h>

using namespace nvcuda;

#define BATCH 32768
#define NLEN  1116
#define HDIM  100

// ---------------------------------------------------------------------------
// sym4 filters
// ---------------------------------------------------------------------------
__constant__ float c_LO[8] = {
    -0.010597401784997278f,  0.032883011666982945f,  0.030841381835986965f,
    -0.18703481171888114f,  -0.02798376941698385f,   0.6308807679295904f,
     0.7148465705525415f,    0.23037781330885523f};
__constant__ float c_HI[8] = {
    -0.23037781330885523f,   0.7148465705525415f,   -0.6308807679295904f,
    -0.02798376941698385f,   0.18703481171888114f,   0.030841381835986965f,
    -0.032883011666982945f, -0.010597401784997278f};

__device__ __forceinline__ float softt(float v, float t) {
    float av = fabsf(v);
    return (av > t) ? copysignf(av - t, v) : 0.0f;
}

// One DWT level, COMPILE-TIME size M, T threads. Fully unrolled inner loop.
template <int T, int M>
__device__ __forceinline__ void dwt_level(const float* cur, float* nxt, float* dd,
                                          int id, float t)
{
    constexpr int CH = ((M + T - 1) / T) | 1;   // odd -> <=2-way LDS conflicts
    const int j0 = id * CH;
    if (j0 < M) {
        const float* p = cur + 2 + 2 * j0;
        float w0 = p[0], w1 = p[1], w2 = p[2], w3 = p[3];
        float w4 = p[4], w5 = p[5], w6 = p[6], w7 = p[7];
#pragma unroll
        for (int jj = 0; jj < CH; ++jj) {
            const int j = j0 + jj;
            float lo = w0 * c_LO[7];
            lo = fmaf(w1, c_LO[6], lo); lo = fmaf(w2, c_LO[5], lo);
            lo = fmaf(w3, c_LO[4], lo); lo = fmaf(w4, c_LO[3], lo);
            lo = fmaf(w5, c_LO[2], lo); lo = fmaf(w6, c_LO[1], lo);
            lo = fmaf(w7, c_LO[0], lo);
            float hi = w0 * c_HI[7];
            hi = fmaf(w1, c_HI[6], hi); hi = fmaf(w2, c_HI[5], hi);
            hi = fmaf(w3, c_HI[4], hi); hi = fmaf(w4, c_HI[3], hi);
            hi = fmaf(w5, c_HI[2], hi); hi = fmaf(w6, c_HI[1], hi);
            hi = fmaf(w7, c_HI[0], hi);
            if (j < M) {
                nxt[8 + j] = lo;
                dd[j] = softt(hi, t);
            }
            if (jj + 1 < CH) {
                w0 = w2; w1 = w3; w2 = w4; w3 = w5; w4 = w6; w5 = w7;
                float2 nx = *(const float2*)(p + 8 + 2 * jj);   // immediate offset
                w6 = nx.x; w7 = nx.y;                            // lookahead slack ok
            }
        }
    }
    if (id < 6) nxt[2 + id] = 0.0f;
    if (id < 8) nxt[8 + M + id] = 0.0f;
}

// One IDWT level, COMPILE-TIME pair count P.
template <int T, int P>
__device__ __forceinline__ void idwt_level(const float* abase, const float* dd,
                                           float* obase, int id)
{
    constexpr int CH = ((P + T - 1) / T) | 1;
    const int p0 = id * CH;
    if (p0 < P) {
        float a0 = abase[p0], a1 = abase[p0 + 1], a2 = abase[p0 + 2], a3 = abase[p0 + 3];
        float d0 = dd[p0],    d1 = dd[p0 + 1],    d2 = dd[p0 + 2],    d3 = dd[p0 + 3];
#pragma unroll
        for (int jj = 0; jj < CH; ++jj) {
            const int p = p0 + jj;
            float ye = a0 * c_LO[1];
            ye = fmaf(a1, c_LO[3], ye); ye = fmaf(a2, c_LO[5], ye); ye = fmaf(a3, c_LO[7], ye);
            ye = fmaf(d0, c_HI[1], ye); ye = fmaf(d1, c_HI[3], ye);
            ye = fmaf(d2, c_HI[5], ye); ye = fmaf(d3, c_HI[7], ye);
            float yo = a0 * c_LO[0];
            yo = fmaf(a1, c_LO[2], yo); yo = fmaf(a2, c_LO[4], yo); yo = fmaf(a3, c_LO[6], yo);
            yo = fmaf(d0, c_HI[0], yo); yo = fmaf(d1, c_HI[2], yo);
            yo = fmaf(d2, c_HI[4], yo); yo = fmaf(d3, c_HI[6], yo);
            if (p < P) ((float2*)obase)[p] = make_float2(ye, yo);
            if (jj + 1 < CH) {
                a0 = a1; a1 = a2; a2 = a3; a3 = abase[p0 + jj + 4];   // lookahead ok
                d0 = d1; d1 = d2; d2 = d3; d3 = dd[p0 + jj + 4];
            }
        }
    }
}

// ---------------------------------------------------------------------------
// Kernel 1: per-row 7-level DWT -> soft threshold -> IDWT. (unchanged R11)
// ---------------------------------------------------------------------------
__global__ __launch_bounds__(128) void wavelet_kernel(
    const float* __restrict__ x,
    const float* __restrict__ thr,
    float* __restrict__ recon)
{
    __shared__ __align__(16) float bufA[1140];
    __shared__ __align__(16) float bufB[1140];
    __shared__ __align__(16) float dbuf[1152];

    const int tid = threadIdx.x;
    const int row = blockIdx.x;
    const float t = fmaxf(thr[0], 0.01f);

    {
        const float4* xr = (const float4*)(x + (size_t)row * NLEN);
        float4* dst = (float4*)(bufA + 8);
        for (int i = tid; i < 279; i += 128) dst[i] = xr[i];
        if (tid < 6) bufA[2 + tid] = 0.0f;
        if (tid < 8) bufA[8 + NLEN + tid] = 0.0f;
    }
    __syncthreads();

    dwt_level<128, 561>(bufA, bufB, dbuf + 0,   tid, t);
    __syncthreads();
    dwt_level<128, 284>(bufB, bufA, dbuf + 561, tid, t);
    __syncthreads();
    dwt_level<128, 145>(bufA, bufB, dbuf + 845, tid, t);
    __syncthreads();

    if (tid < 32) {
        const int lane = tid;
        dwt_level<32, 76>(bufB, bufA, dbuf + 990,  lane, t);
        __syncwarp();
        dwt_level<32, 41>(bufA, bufB, dbuf + 1066, lane, t);
        __syncwarp();
        dwt_level<32, 24>(bufB, bufA, dbuf + 1107, lane, t);
        __syncwarp();
        dwt_level<32, 15>(bufA, bufB, dbuf + 1131, lane, t);
        __syncwarp();
        if (lane < 15) bufB[8 + lane] = softt(bufB[8 + lane], t);
        __syncwarp();
        idwt_level<32, 12>(bufB + 8, dbuf + 1131, bufA, lane);
        __syncwarp();
        idwt_level<32, 21>(bufA, dbuf + 1107, bufB, lane);
        __syncwarp();
        idwt_level<32, 38>(bufB, dbuf + 1066, bufA, lane);
    }
    __syncthreads();

    idwt_level<128, 73>(bufA, dbuf + 990, bufB, tid);
    __syncthreads();
    idwt_level<128, 142>(bufB, dbuf + 845, bufA, tid);
    __syncthreads();
    idwt_level<128, 281>(bufA, dbuf + 561, bufB, tid);
    __syncthreads();
    idwt_level<128, 558>(bufB, dbuf + 0, bufA, tid);
    __syncthreads();

    {
        float4* out = (float4*)(recon + (size_t)row * NLEN);
        const float4* a4 = (const float4*)bufA;
        for (int i = tid; i < 279; i += 128) out[i] = a4[i];
    }
}

// ---------------------------------------------------------------------------
// W1 split precompute: hi/lo bf16 panels [35][112][32] (unchanged)
// ---------------------------------------------------------------------------
#define KP2  35
#define NPAD 112
#define BTOT (KP2 * NPAD * 32)
__device__ __nv_bfloat16 g_Bhi[BTOT];
__device__ __nv_bfloat16 g_Blo[BTOT];

__global__ __launch_bounds__(256) void w1_split_kernel(const float* __restrict__ W1)
{
    int i = blockIdx.x * 256 + threadIdx.x;
    if (i >= BTOT) return;
    int kk = i & 31;
    int n  = (i >> 5) % NPAD;
    int p  = i / (NPAD * 32);
    int k  = p * 32 + kk;
    float v = (n < HDIM && k < NLEN) ? W1[(size_t)n * NLEN + k] : 0.0f;
    __nv_bfloat16 h = __float2bfloat16(v);
    g_Bhi[i] = h;
    g_Blo[i] = __float2bfloat16(v - __bfloat162float(h));
}

// ---------------------------------------------------------------------------
// Kernel 2: wmma bf16 GEMM, 2-TERM split: D = A_bf16 * (Bhi + Blo).
// A in plain bf16 (error alo*b ~ 2^-9, global rel err ~5e-6 << 1e-3).
// Block: 128 rows x 112 cols, BK=32 (35 panels), 512 threads = 16 warps.
// Single-stage, register prefetch of next A (GMEM) and B (L2) panels.
// ---------------------------------------------------------------------------
#define GBM 128
#define GTHREADS 512
#define ALD 40      // A smem ld (elements)
#define BLD 40      // B smem ld (elements, stride between n columns)
#define ELD 120     // epilogue smem ld (floats)
// dynamic smem: union( A(10240)+B(17920)=28160 , eps 128*120*4=61440 )
#define GEMM_SMEM (GBM * ELD * 4)

__global__ __launch_bounds__(GTHREADS) void mlp_wmma_kernel(
    const float* __restrict__ recon,
    const float* __restrict__ b1,
    const float* __restrict__ W2,
    const float* __restrict__ b2,
    float* __restrict__ reg)
{
    extern __shared__ __align__(16) char smem[];
    __shared__ float b1s[NPAD];
    __shared__ float w2s[NPAD];

    __nv_bfloat16* Abf = (__nv_bfloat16*)(smem);              // [128][40] 10240 B
    char* BhiB = smem + 10240;                                 // [112][40]  8960 B
    char* BloB = smem + 19200;                                 // [112][40]  8960 B
    float* eps = (float*)smem;                                 // [128][120]

    const int tid = threadIdx.x;
    const int wid = tid >> 5;
    const int wm = wid >> 1;      // m-tile 0..7
    const int wn = wid & 1;       // n-half 0..1
    const int NT = wn ? 3 : 4;    // tiles in this half (cols 0..63 / 64..111)
    const int row0 = blockIdx.x * GBM;

    if (tid < NPAD) {
        b1s[tid] = (tid < HDIM) ? b1[tid] : 0.0f;
        w2s[tid] = (tid < HDIM) ? W2[tid] : 0.0f;
    }

    wmma::fragment<wmma::accumulator, 16, 16, 16, float> acc[4];
#pragma unroll
    for (int nt = 0; nt < 4; ++nt) wmma::fill_fragment(acc[nt], 0.0f);

    const int r = tid >> 2;       // 0..127 : A row this thread loads
    const int q = tid & 3;        // 0..3   : which 8-float chunk of the 32-k panel
    const int bj = tid;           // B copy index (tid < 448 active)

    // --- prefetch registers
    float4 va0, va1;
    uint4 vbh0, vbl0;
    const float* arow = recon + (size_t)(row0 + r) * NLEN + q * 8;
    {   // panel 0 (always full)
        va0 = *(const float4*)(arow);
        va1 = *(const float4*)(arow + 4);
        if (bj < 448) {
            vbh0 = ((const uint4*)g_Bhi)[bj];
            vbl0 = ((const uint4*)g_Blo)[bj];
        }
    }

    for (int p = 0; p < KP2; ++p) {
        // ---- convert & store A panel p (plain bf16)
        {
            __nv_bfloat162 hp0(__float2bfloat16(va0.x), __float2bfloat16(va0.y));
            __nv_bfloat162 hp1(__float2bfloat16(va0.z), __float2bfloat16(va0.w));
            __nv_bfloat162 hp2(__float2bfloat16(va1.x), __float2bfloat16(va1.y));
            __nv_bfloat162 hp3(__float2bfloat16(va1.z), __float2bfloat16(va1.w));
            const int o = r * ALD + q * 8;       // element offset (16B aligned)
            *(uint4*)(Abf + o) = make_uint4(*(uint32_t*)&hp0, *(uint32_t*)&hp1,
                                            *(uint32_t*)&hp2, *(uint32_t*)&hp3);
        }
        // ---- store B panel p from registers
        if (bj < 448) {
            const int n = bj >> 2, kq = bj & 3;
            *(uint4*)(BhiB + (n * BLD + kq * 8) * 2) = vbh0;
            *(uint4*)(BloB + (n * BLD + kq * 8) * 2) = vbl0;
        }
        __syncthreads();

        // ---- prefetch next panel (A from GMEM, B from L2) while MMAs run
        if (p + 1 < KP2) {
            const float* src = arow + (p + 1) * 32;
            if (p + 1 == KP2 - 1 && q == 3) {          // k = 1112..1119: last 4 pad
                va0 = *(const float4*)(src);
                va1 = make_float4(0.f, 0.f, 0.f, 0.f);
            } else {
                va0 = *(const float4*)(src);
                va1 = *(const float4*)(src + 4);
            }
            if (bj < 448) {
                vbh0 = ((const uint4*)g_Bhi)[(p + 1) * 448 + bj];
                vbl0 = ((const uint4*)g_Blo)[(p + 1) * 448 + bj];
            }
        }

        // ---- MMAs: 2 k-steps of 16, 2 terms each
#pragma unroll
        for (int ks = 0; ks < 2; ++ks) {
            wmma::fragment<wmma::matrix_a, 16, 16, 16, __nv_bfloat16, wmma::row_major> fa;
            wmma::load_matrix_sync(fa, Abf + wm * 16 * ALD + ks * 16, ALD);
#pragma unroll
            for (int nt = 0; nt < 4; ++nt) {
                if (nt < NT) {
                    const int n0 = (wn * 4 + nt) * 16;
                    wmma::fragment<wmma::matrix_b, 16, 16, 16, __nv_bfloat16, wmma::col_major> fb_hi, fb_lo;
                    wmma::load_matrix_sync(fb_hi, (__nv_bfloat16*)BhiB + n0 * BLD + ks * 16, BLD);
                    wmma::load_matrix_sync(fb_lo, (__nv_bfloat16*)BloB + n0 * BLD + ks * 16, BLD);
                    wmma::mma_sync(acc[nt], fa, fb_hi, acc[nt]);
                    wmma::mma_sync(acc[nt], fa, fb_lo, acc[nt]);
                }
            }
        }
        __syncthreads();
    }

    // ---- epilogue: dump accumulators, sigmoid + W2 reduce
#pragma unroll
    for (int nt = 0; nt < 4; ++nt) {
        if (nt < NT) {
            wmma::store_matrix_sync(eps + wm * 16 * ELD + (wn * 4 + nt) * 16,
                                    acc[nt], ELD, wmma::mem_row_major);
        }
    }
    __syncthreads();

    {
        const float* er = eps + r * ELD;
        float s = 0.0f;
        const int c0 = q * 28;
#pragma unroll
        for (int c = 0; c < 28; ++c) {
            float pre = er[c0 + c] + b1s[c0 + c];
            float h = 1.0f / (1.0f + __expf(-pre));
            s = fmaf(h, w2s[c0 + c], s);   // w2s==0 beyond HDIM
        }
        s += __shfl_xor_sync(0xFFFFFFFFu, s, 1);
        s += __shfl_xor_sync(0xFFFFFFFFu, s, 2);
        if (q == 0) reg[row0 + r] = s + b2[0];
    }
}

// ---------------------------------------------------------------------------
extern "C" void kernel_launch(void* const* d_in, const int* in_sizes, int n_in,
                              void* d_out, int out_size)
{
    const float* x   = (const float*)d_in[0];
    const float* thr = (const float*)d_in[1];
    const float* W1  = (const float*)d_in[2];
    const float* b1  = (const float*)d_in[3];
    const float* W2  = (const float*)d_in[4];
    const float* b2  = (const float*)d_in[5];

    float* recon = (float*)d_out;
    float* reg   = (float*)d_out + (size_t)BATCH * NLEN;

    cudaFuncSetAttribute(mlp_wmma_kernel,
                         cudaFuncAttributeMaxDynamicSharedMemorySize, GEMM_SMEM);

    wavelet_kernel<<<BATCH, 128>>>(x, thr, recon);
    w1_split_kernel<<<(BTOT + 255) / 256, 256>>>(W1);
    mlp_wmma_kernel<<<BATCH / GBM, GTHREADS, GEMM_SMEM>>>(recon, b1, W2, b2, reg);
}

// round 13
// speedup vs baseline: 1.7971x; 1.2432x over previous
#include <cuda_runtime.h>
#include <cuda_fp16.h>
#include <mma.h>
#include <cstdint>
#include <math.h>

using namespace nvcuda;

#define BATCH 32768
#define NLEN  1116
#define HDIM  100

// ---------------------------------------------------------------------------
// sym4 filters
// ---------------------------------------------------------------------------
__constant__ float c_LO[8] = {
    -0.010597401784997278f,  0.032883011666982945f,  0.030841381835986965f,
    -0.18703481171888114f,  -0.02798376941698385f,   0.6308807679295904f,
     0.7148465705525415f,    0.23037781330885523f};
__constant__ float c_HI[8] = {
    -0.23037781330885523f,   0.7148465705525415f,   -0.6308807679295904f,
    -0.02798376941698385f,   0.18703481171888114f,   0.030841381835986965f,
    -0.032883011666982945f, -0.010597401784997278f};

__device__ __forceinline__ float softt(float v, float t) {
    float av = fabsf(v);
    return (av > t) ? copysignf(av - t, v) : 0.0f;
}

// One DWT level, COMPILE-TIME size M, T threads. Fully unrolled inner loop.
template <int T, int M>
__device__ __forceinline__ void dwt_level(const float* cur, float* nxt, float* dd,
                                          int id, float t)
{
    constexpr int CH = ((M + T - 1) / T) | 1;   // odd -> <=2-way LDS conflicts
    const int j0 = id * CH;
    if (j0 < M) {
        const float* p = cur + 2 + 2 * j0;
        float w0 = p[0], w1 = p[1], w2 = p[2], w3 = p[3];
        float w4 = p[4], w5 = p[5], w6 = p[6], w7 = p[7];
#pragma unroll
        for (int jj = 0; jj < CH; ++jj) {
            const int j = j0 + jj;
            float lo = w0 * c_LO[7];
            lo = fmaf(w1, c_LO[6], lo); lo = fmaf(w2, c_LO[5], lo);
            lo = fmaf(w3, c_LO[4], lo); lo = fmaf(w4, c_LO[3], lo);
            lo = fmaf(w5, c_LO[2], lo); lo = fmaf(w6, c_LO[1], lo);
            lo = fmaf(w7, c_LO[0], lo);
            float hi = w0 * c_HI[7];
            hi = fmaf(w1, c_HI[6], hi); hi = fmaf(w2, c_HI[5], hi);
            hi = fmaf(w3, c_HI[4], hi); hi = fmaf(w4, c_HI[3], hi);
            hi = fmaf(w5, c_HI[2], hi); hi = fmaf(w6, c_HI[1], hi);
            hi = fmaf(w7, c_HI[0], hi);
            if (j < M) {
                nxt[8 + j] = lo;
                dd[j] = softt(hi, t);
            }
            if (jj + 1 < CH) {
                w0 = w2; w1 = w3; w2 = w4; w3 = w5; w4 = w6; w5 = w7;
                float2 nx = *(const float2*)(p + 8 + 2 * jj);   // immediate offset
                w6 = nx.x; w7 = nx.y;                            // lookahead slack ok
            }
        }
    }
    if (id < 6) nxt[2 + id] = 0.0f;
    if (id < 8) nxt[8 + M + id] = 0.0f;
}

// One IDWT level, COMPILE-TIME pair count P.
template <int T, int P>
__device__ __forceinline__ void idwt_level(const float* abase, const float* dd,
                                           float* obase, int id)
{
    constexpr int CH = ((P + T - 1) / T) | 1;
    const int p0 = id * CH;
    if (p0 < P) {
        float a0 = abase[p0], a1 = abase[p0 + 1], a2 = abase[p0 + 2], a3 = abase[p0 + 3];
        float d0 = dd[p0],    d1 = dd[p0 + 1],    d2 = dd[p0 + 2],    d3 = dd[p0 + 3];
#pragma unroll
        for (int jj = 0; jj < CH; ++jj) {
            const int p = p0 + jj;
            float ye = a0 * c_LO[1];
            ye = fmaf(a1, c_LO[3], ye); ye = fmaf(a2, c_LO[5], ye); ye = fmaf(a3, c_LO[7], ye);
            ye = fmaf(d0, c_HI[1], ye); ye = fmaf(d1, c_HI[3], ye);
            ye = fmaf(d2, c_HI[5], ye); ye = fmaf(d3, c_HI[7], ye);
            float yo = a0 * c_LO[0];
            yo = fmaf(a1, c_LO[2], yo); yo = fmaf(a2, c_LO[4], yo); yo = fmaf(a3, c_LO[6], yo);
            yo = fmaf(d0, c_HI[0], yo); yo = fmaf(d1, c_HI[2], yo);
            yo = fmaf(d2, c_HI[4], yo); yo = fmaf(d3, c_HI[6], yo);
            if (p < P) ((float2*)obase)[p] = make_float2(ye, yo);
            if (jj + 1 < CH) {
                a0 = a1; a1 = a2; a2 = a3; a3 = abase[p0 + jj + 4];   // lookahead ok
                d0 = d1; d1 = d2; d2 = d3; d3 = dd[p0 + jj + 4];
            }
        }
    }
}

// ---------------------------------------------------------------------------
// Kernel 1: per-row 7-level DWT -> soft threshold -> IDWT. (unchanged R11)
// ---------------------------------------------------------------------------
__global__ __launch_bounds__(128) void wavelet_kernel(
    const float* __restrict__ x,
    const float* __restrict__ thr,
    float* __restrict__ recon)
{
    __shared__ __align__(16) float bufA[1140];
    __shared__ __align__(16) float bufB[1140];
    __shared__ __align__(16) float dbuf[1152];

    const int tid = threadIdx.x;
    const int row = blockIdx.x;
    const float t = fmaxf(thr[0], 0.01f);

    {
        const float4* xr = (const float4*)(x + (size_t)row * NLEN);
        float4* dst = (float4*)(bufA + 8);
        for (int i = tid; i < 279; i += 128) dst[i] = xr[i];
        if (tid < 6) bufA[2 + tid] = 0.0f;
        if (tid < 8) bufA[8 + NLEN + tid] = 0.0f;
    }
    __syncthreads();

    dwt_level<128, 561>(bufA, bufB, dbuf + 0,   tid, t);
    __syncthreads();
    dwt_level<128, 284>(bufB, bufA, dbuf + 561, tid, t);
    __syncthreads();
    dwt_level<128, 145>(bufA, bufB, dbuf + 845, tid, t);
    __syncthreads();

    if (tid < 32) {
        const int lane = tid;
        dwt_level<32, 76>(bufB, bufA, dbuf + 990,  lane, t);
        __syncwarp();
        dwt_level<32, 41>(bufA, bufB, dbuf + 1066, lane, t);
        __syncwarp();
        dwt_level<32, 24>(bufB, bufA, dbuf + 1107, lane, t);
        __syncwarp();
        dwt_level<32, 15>(bufA, bufB, dbuf + 1131, lane, t);
        __syncwarp();
        if (lane < 15) bufB[8 + lane] = softt(bufB[8 + lane], t);
        __syncwarp();
        idwt_level<32, 12>(bufB + 8, dbuf + 1131, bufA, lane);
        __syncwarp();
        idwt_level<32, 21>(bufA, dbuf + 1107, bufB, lane);
        __syncwarp();
        idwt_level<32, 38>(bufB, dbuf + 1066, bufA, lane);
    }
    __syncthreads();

    idwt_level<128, 73>(bufA, dbuf + 990, bufB, tid);
    __syncthreads();
    idwt_level<128, 142>(bufB, dbuf + 845, bufA, tid);
    __syncthreads();
    idwt_level<128, 281>(bufA, dbuf + 561, bufB, tid);
    __syncthreads();
    idwt_level<128, 558>(bufB, dbuf + 0, bufA, tid);
    __syncthreads();

    {
        float4* out = (float4*)(recon + (size_t)row * NLEN);
        const float4* a4 = (const float4*)bufA;
        for (int i = tid; i < 279; i += 128) out[i] = a4[i];
    }
}

// ---------------------------------------------------------------------------
// W1 fp16 precompute: panels [35][112][32] (n padded to 112, k padded to
// 1120), k-panel-major so GEMM copies are contiguous uint4s.
// ---------------------------------------------------------------------------
#define KP2  35
#define NPAD 112
#define BTOT (KP2 * NPAD * 32)
__device__ __half g_Bh[BTOT];

__global__ __launch_bounds__(256) void w1_split_kernel(const float* __restrict__ W1)
{
    int i = blockIdx.x * 256 + threadIdx.x;
    if (i >= BTOT) return;
    int kk = i & 31;
    int n  = (i >> 5) % NPAD;
    int p  = i / (NPAD * 32);
    int k  = p * 32 + kk;
    float v = (n < HDIM && k < NLEN) ? W1[(size_t)n * NLEN + k] : 0.0f;
    g_Bh[i] = __float2half(v);
}

// ---------------------------------------------------------------------------
// Kernel 2: wmma fp16 GEMM (single term) + fused sigmoid/W2 reduction.
// fp16 RN error 2^-11 (8x smaller than bf16 2^-8) -> calibrated rel_err ~1e-4.
// Block: 128 rows x 112 cols, BK=32 (35 panels), 512 threads = 16 warps.
// Single-stage, register prefetch of next A (GMEM) and B (L2) panels.
// ---------------------------------------------------------------------------
#define GBM 128
#define GTHREADS 512
#define ALD 40      // A smem ld (elements)
#define BLD 40      // B smem ld (elements, stride between n columns)
#define ELD 120     // epilogue smem ld (floats)
// dynamic smem: union( A(10240)+B(8960)=19200 , eps 128*120*4=61440 )
#define GEMM_SMEM (GBM * ELD * 4)

__global__ __launch_bounds__(GTHREADS) void mlp_wmma_kernel(
    const float* __restrict__ recon,
    const float* __restrict__ b1,
    const float* __restrict__ W2,
    const float* __restrict__ b2,
    float* __restrict__ reg)
{
    extern __shared__ __align__(16) char smem[];
    __shared__ float b1s[NPAD];
    __shared__ float w2s[NPAD];

    __half* Ah = (__half*)(smem);              // [128][40] 10240 B
    char* BhB  = smem + 10240;                 // [112][40]  8960 B
    float* eps = (float*)smem;                 // [128][120]

    const int tid = threadIdx.x;
    const int wid = tid >> 5;
    const int wm = wid >> 1;      // m-tile 0..7
    const int wn = wid & 1;       // n-half 0..1
    const int NT = wn ? 3 : 4;    // tiles in this half (cols 0..63 / 64..111)
    const int row0 = blockIdx.x * GBM;

    if (tid < NPAD) {
        b1s[tid] = (tid < HDIM) ? b1[tid] : 0.0f;
        w2s[tid] = (tid < HDIM) ? W2[tid] : 0.0f;
    }

    wmma::fragment<wmma::accumulator, 16, 16, 16, float> acc[4];
#pragma unroll
    for (int nt = 0; nt < 4; ++nt) wmma::fill_fragment(acc[nt], 0.0f);

    const int r = tid >> 2;       // 0..127 : A row this thread loads
    const int q = tid & 3;        // 0..3   : which 8-float chunk of the 32-k panel
    const int bj = tid;           // B copy index (tid < 448 active)

    // --- prefetch registers
    float4 va0, va1;
    uint4 vbh0;
    const float* arow = recon + (size_t)(row0 + r) * NLEN + q * 8;
    {   // panel 0 (always full)
        va0 = *(const float4*)(arow);
        va1 = *(const float4*)(arow + 4);
        if (bj < 448) vbh0 = ((const uint4*)g_Bh)[bj];
    }

    for (int p = 0; p < KP2; ++p) {
        // ---- convert & store A panel p (fp16)
        {
            __half2 hp0 = __floats2half2_rn(va0.x, va0.y);
            __half2 hp1 = __floats2half2_rn(va0.z, va0.w);
            __half2 hp2 = __floats2half2_rn(va1.x, va1.y);
            __half2 hp3 = __floats2half2_rn(va1.z, va1.w);
            const int o = r * ALD + q * 8;       // element offset (16B aligned)
            *(uint4*)(Ah + o) = make_uint4(*(uint32_t*)&hp0, *(uint32_t*)&hp1,
                                           *(uint32_t*)&hp2, *(uint32_t*)&hp3);
        }
        // ---- store B panel p from registers
        if (bj < 448) {
            const int n = bj >> 2, kq = bj & 3;
            *(uint4*)(BhB + (n * BLD + kq * 8) * 2) = vbh0;
        }
        __syncthreads();

        // ---- prefetch next panel (A from GMEM, B from L2) while MMAs run
        if (p + 1 < KP2) {
            const float* src = arow + (p + 1) * 32;
            if (p + 1 == KP2 - 1 && q == 3) {          // k = 1112..1119: last 4 pad
                va0 = *(const float4*)(src);
                va1 = make_float4(0.f, 0.f, 0.f, 0.f);
            } else {
                va0 = *(const float4*)(src);
                va1 = *(const float4*)(src + 4);
            }
            if (bj < 448) vbh0 = ((const uint4*)g_Bh)[(p + 1) * 448 + bj];
        }

        // ---- MMAs: 2 k-steps of 16, single term
#pragma unroll
        for (int ks = 0; ks < 2; ++ks) {
            wmma::fragment<wmma::matrix_a, 16, 16, 16, __half, wmma::row_major> fa;
            wmma::load_matrix_sync(fa, Ah + wm * 16 * ALD + ks * 16, ALD);
#pragma unroll
            for (int nt = 0; nt < 4; ++nt) {
                if (nt < NT) {
                    const int n0 = (wn * 4 + nt) * 16;
                    wmma::fragment<wmma::matrix_b, 16, 16, 16, __half, wmma::col_major> fb;
                    wmma::load_matrix_sync(fb, (__half*)BhB + n0 * BLD + ks * 16, BLD);
                    wmma::mma_sync(acc[nt], fa, fb, acc[nt]);
                }
            }
        }
        __syncthreads();
    }

    // ---- epilogue: dump accumulators, sigmoid + W2 reduce
#pragma unroll
    for (int nt = 0; nt < 4; ++nt) {
        if (nt < NT) {
            wmma::store_matrix_sync(eps + wm * 16 * ELD + (wn * 4 + nt) * 16,
                                    acc[nt], ELD, wmma::mem_row_major);
        }
    }
    __syncthreads();

    {
        const float* er = eps + r * ELD;
        float s = 0.0f;
        const int c0 = q * 28;
#pragma unroll
        for (int c = 0; c < 28; ++c) {
            float pre = er[c0 + c] + b1s[c0 + c];
            float h = 1.0f / (1.0f + __expf(-pre));
            s = fmaf(h, w2s[c0 + c], s);   // w2s==0 beyond HDIM
        }
        s += __shfl_xor_sync(0xFFFFFFFFu, s, 1);
        s += __shfl_xor_sync(0xFFFFFFFFu, s, 2);
        if (q == 0) reg[row0 + r] = s + b2[0];
    }
}

// ---------------------------------------------------------------------------
extern "C" void kernel_launch(void* const* d_in, const int* in_sizes, int n_in,
                              void* d_out, int out_size)
{
    const float* x   = (const float*)d_in[0];
    const float* thr = (const float*)d_in[1];
    const float* W1  = (const float*)d_in[2];
    const float* b1  = (const float*)d_in[3];
    const float* W2  = (const float*)d_in[4];
    const float* b2  = (const float*)d_in[5];

    float* recon = (float*)d_out;
    float* reg   = (float*)d_out + (size_t)BATCH * NLEN;

    cudaFuncSetAttribute(mlp_wmma_kernel,
                         cudaFuncAttributeMaxDynamicSharedMemorySize, GEMM_SMEM);

    wavelet_kernel<<<BATCH, 128>>>(x, thr, recon);
    w1_split_kernel<<<(BTOT + 255) / 256, 256>>>(W1);
    mlp_wmma_kernel<<<BATCH / GBM, GTHREADS, GEMM_SMEM>>>(recon, b1, W2, b2, reg);
}